// round 14
// baseline (speedup 1.0000x reference)
#include <cuda_runtime.h>

#define PAIRS_PER_BLOCK 16
#define NTHREADS (PAIRS_PER_BLOCK * 8)   // 128 threads, 4 warps, no block-wide syncs
#define SLOT 536            // floats per pair slot; 536 % 32 == 24 -> warp group bases {0,24,16,8}
#define BSTRIDE 268         // floats per batch inside slot; 268 % 32 == 12

typedef unsigned long long u64;
typedef unsigned int u32;

struct WPack {
    float w1[32][16];
    float wbT[32][8];
    float w2[16][8];
    float wg[8][8];
    float bb[8];
    float b1[16];
    float b2[8];
    float bg[8];
    float wf[16];
    float bf[2];
};

__constant__ WPack c_w;

// Prep writes packed/transposed weights DIRECTLY into c_w's backing store.
__global__ void prep_kernel(WPack* __restrict__ cw,
                            const float* __restrict__ wb, const float* __restrict__ bb,
                            const float* __restrict__ w1, const float* __restrict__ b1,
                            const float* __restrict__ w2, const float* __restrict__ b2,
                            const float* __restrict__ wg, const float* __restrict__ bg,
                            const float* __restrict__ wf, const float* __restrict__ bf)
{
    int t = threadIdx.x;
    for (int i = t; i < 512; i += blockDim.x) ((float*)cw->w1)[i] = w1[i];
    for (int i = t; i < 256; i += blockDim.x) {
        int c = i >> 3, o = i & 7;
        cw->wbT[c][o] = wb[o * 32 + c];
    }
    for (int i = t; i < 128; i += blockDim.x) ((float*)cw->w2)[i] = w2[i];
    if (t < 64) ((float*)cw->wg)[t] = wg[t];
    if (t < 16) { cw->b1[t] = b1[t]; cw->wf[t] = wf[t]; }
    if (t < 8)  { cw->bb[t] = bb[t]; cw->b2[t] = b2[t]; cw->bg[t] = bg[t]; }
    if (t < 2)  { cw->bf[t] = bf[t]; }
}

__device__ __forceinline__ u64 pk2(float a, float b) {
    u64 r; asm("mov.b64 %0,{%1,%2};" : "=l"(r) : "f"(a), "f"(b)); return r;
}
__device__ __forceinline__ u64 pk1(float a) { return pk2(a, a); }
__device__ __forceinline__ void up2(u64 v, float& a, float& b) {
    asm("mov.b64 {%0,%1},%2;" : "=f"(a), "=f"(b) : "l"(v));
}
__device__ __forceinline__ u64 fma2_(u64 a, u64 b, u64 c) {
    u64 d; asm("fma.rn.f32x2 %0,%1,%2,%3;" : "=l"(d) : "l"(a), "l"(b), "l"(c)); return d;
}
__device__ __forceinline__ u64 add2_(u64 a, u64 b) {
    u64 d; asm("add.rn.f32x2 %0,%1,%2;" : "=l"(d) : "l"(a), "l"(b)); return d;
}
__device__ __forceinline__ u64 mul2_(u64 a, u64 b) {
    u64 d; asm("mul.rn.f32x2 %0,%1,%2;" : "=l"(d) : "l"(a), "l"(b)); return d;
}
__device__ __forceinline__ u64 shfl_xor64(u64 v, int m) {
    return __shfl_xor_sync(0xffffffffu, v, m, 32);
}
__device__ __forceinline__ u32 smem_u32(const void* p) {
    u32 a;
    asm("{ .reg .u64 t; cvta.to.shared.u64 t, %1; cvt.u32.u64 %0, t; }"
        : "=r"(a) : "l"(p));
    return a;
}
__device__ __forceinline__ float lrelu(float x) { return fmaxf(x, 0.01f * x); }

__global__ void __launch_bounds__(NTHREADS, 6)
gcn_kernel(const float* __restrict__ x,   const float* __restrict__ adj,
           const float* __restrict__ edge,
           float* __restrict__ out)
{
    // Per-pair slot (SLOT floats):
    //  Phase A (x stage via cp.async): batch bb at bb*BSTRIDE .. +263
    //  Phase B aliases x region: FkT 0..127, S->q 128..255, p->h2 256..511
    __shared__ __align__(16) float s_u[PAIRS_PER_BLOCK * SLOT];

    const int tid = threadIdx.x;
    const int g = tid >> 3;                      // 0..15
    const int v = tid & 7;
    const size_t pair = (size_t)blockIdx.x * PAIRS_PER_BLOCK + g;
    const size_t b0 = pair * 2;

    // L2 prefetch of adj/edge rows consumed ~1500 cycles later at W-build;
    // overlaps DRAM latency with phase-1 compute at zero register cost.
    #pragma unroll
    for (int b = 0; b < 2; b++) {
        asm volatile("prefetch.global.L2 [%0];" :: "l"(adj  + (b0 + b) * 64 + v * 8));
        asm volatile("prefetch.global.L2 [%0];" :: "l"(edge + (b0 + b) * 64 + v * 8));
    }

    {   // warp-local, div-free cp.async staging: lane owns (batch, float4-column)
        const int lane = tid & 31;
        const int wrp  = tid >> 5;               // 0..3
        const int bl   = lane >> 2;              // local batch within warp: 0..7
        const int pr   = wrp * 4 + (bl >> 1);    // pair slot within block: 0..15
        const int bbx  = bl & 1;
        const int jb   = lane & 3;               // float4 column phase
        const float4* src = (const float4*)(x + (size_t)blockIdx.x * (PAIRS_PER_BLOCK * 2 * 264))
                            + (size_t)(wrp * 8 + bl) * 66 + jb;
        u32 dst = smem_u32(s_u) + (u32)(pr * SLOT + bbx * BSTRIDE + jb * 4) * 4u;
        #pragma unroll
        for (int k = 0; k < 16; k++) {
            asm volatile("cp.async.cg.shared.global [%0], [%1], 16;"
                         :: "r"(dst), "l"(src));
            dst += 64; src += 4;
        }
        if (jb < 2) {   // j = jb + 64 in {64,65} < 66
            asm volatile("cp.async.cg.shared.global [%0], [%1], 16;"
                         :: "r"(dst), "l"(src));
        }
        asm volatile("cp.async.commit_group;");
        asm volatile("cp.async.wait_group 0;");
    }
    __syncwarp();   // staging is warp-private -> no block barrier needed

    float* Xg = s_u + g * SLOT;

    // node types for THIS thread's node -> registers (pool peers come via shfl)
    float tyR[2];
    tyR[0] = Xg[0 * BSTRIDE + v * 33];
    tyR[1] = Xg[1 * BSTRIDE + v * 33];

    // ================= phase 1: Fk column v (o-paired), p row v (j-paired)
    u64 Fk[2][4], p[2][8];
    #pragma unroll
    for (int i = 0; i < 4; i++) { Fk[0][i] = 0ull; Fk[1][i] = 0ull; }
    #pragma unroll
    for (int i = 0; i < 8; i++) { p[0][i] = 0ull; p[1][i] = 0ull; }

    const float* f0 = Xg + 0 * BSTRIDE + v * 33 + 1;
    const float* f1 = Xg + 1 * BSTRIDE + v * 33 + 1;
    #pragma unroll 8
    for (int c = 0; c < 32; c++) {
        u64 q0 = pk1(f0[c]), q1 = pk1(f1[c]);
        const ulonglong2* w1r = (const ulonglong2*)c_w.w1[c];
        const ulonglong2* wbr = (const ulonglong2*)c_w.wbT[c];
        #pragma unroll
        for (int jj = 0; jj < 4; jj++) {
            ulonglong2 w = w1r[jj];
            p[0][jj * 2]     = fma2_(q0, w.x, p[0][jj * 2]);
            p[0][jj * 2 + 1] = fma2_(q0, w.y, p[0][jj * 2 + 1]);
            p[1][jj * 2]     = fma2_(q1, w.x, p[1][jj * 2]);
            p[1][jj * 2 + 1] = fma2_(q1, w.y, p[1][jj * 2 + 1]);
        }
        #pragma unroll
        for (int oo = 0; oo < 2; oo++) {
            ulonglong2 w = wbr[oo];
            Fk[0][oo * 2]     = fma2_(q0, w.x, Fk[0][oo * 2]);
            Fk[0][oo * 2 + 1] = fma2_(q0, w.y, Fk[0][oo * 2 + 1]);
            Fk[1][oo * 2]     = fma2_(q1, w.x, Fk[1][oo * 2]);
            Fk[1][oo * 2 + 1] = fma2_(q1, w.y, Fk[1][oo * 2 + 1]);
        }
    }
    #pragma unroll
    for (int i = 0; i < 4; i++) {
        u64 bbp = ((const u64*)c_w.bb)[i];
        Fk[0][i] = add2_(Fk[0][i], bbp);
        Fk[1][i] = add2_(Fk[1][i], bbp);
    }

    __syncwarp();   // feat reads done -> alias x region
    {
        ulonglong2* d0 = (ulonglong2*)((u64*)Xg + v * 4);
        d0[0] = make_ulonglong2(Fk[0][0], Fk[0][1]);
        d0[1] = make_ulonglong2(Fk[0][2], Fk[0][3]);
        ulonglong2* d1 = (ulonglong2*)((u64*)Xg + 32 + v * 4);
        d1[0] = make_ulonglong2(Fk[1][0], Fk[1][1]);
        d1[1] = make_ulonglong2(Fk[1][2], Fk[1][3]);
        ulonglong2* p0 = (ulonglong2*)((u64*)(Xg + 256) + v * 8);
        p0[0] = make_ulonglong2(p[0][0], p[0][1]);
        p0[1] = make_ulonglong2(p[0][2], p[0][3]);
        p0[2] = make_ulonglong2(p[0][4], p[0][5]);
        p0[3] = make_ulonglong2(p[0][6], p[0][7]);
        ulonglong2* p1 = (ulonglong2*)((u64*)(Xg + 256) + 64 + v * 8);
        p1[0] = make_ulonglong2(p[1][0], p[1][1]);
        p1[1] = make_ulonglong2(p[1][2], p[1][3]);
        p1[2] = make_ulonglong2(p[1][4], p[1][5]);
        p1[3] = make_ulonglong2(p[1][6], p[1][7]);
    }
    __syncwarp();

    // ================= M column v, softmax over rows (shift-free), write S rows
    {
        float fks[2][8];
        #pragma unroll
        for (int i = 0; i < 4; i++) {
            up2(Fk[0][i], fks[0][2 * i], fks[0][2 * i + 1]);
            up2(Fk[1][i], fks[1][2 * i], fks[1][2 * i + 1]);
        }
        u64 Mv[2][4];
        #pragma unroll
        for (int i = 0; i < 4; i++) { Mv[0][i] = 0ull; Mv[1][i] = 0ull; }
        #pragma unroll
        for (int k = 0; k < 8; k++) {
            ulonglong2 r0a = *(const ulonglong2*)(Xg + k * 8);
            ulonglong2 r0b = *(const ulonglong2*)(Xg + k * 8 + 4);
            ulonglong2 r1a = *(const ulonglong2*)(Xg + 64 + k * 8);
            ulonglong2 r1b = *(const ulonglong2*)(Xg + 64 + k * 8 + 4);
            u64 s0 = pk1(fks[0][k]), s1 = pk1(fks[1][k]);
            Mv[0][0] = fma2_(s0, r0a.x, Mv[0][0]);
            Mv[0][1] = fma2_(s0, r0a.y, Mv[0][1]);
            Mv[0][2] = fma2_(s0, r0b.x, Mv[0][2]);
            Mv[0][3] = fma2_(s0, r0b.y, Mv[0][3]);
            Mv[1][0] = fma2_(s1, r1a.x, Mv[1][0]);
            Mv[1][1] = fma2_(s1, r1a.y, Mv[1][1]);
            Mv[1][2] = fma2_(s1, r1b.x, Mv[1][2]);
            Mv[1][3] = fma2_(s1, r1b.y, Mv[1][3]);
        }
        #pragma unroll
        for (int b = 0; b < 2; b++) {
            float m[8];
            #pragma unroll
            for (int i = 0; i < 4; i++) up2(Mv[b][i], m[2 * i], m[2 * i + 1]);
            float se = 0.f;
            #pragma unroll
            for (int i = 0; i < 8; i++) { m[i] = __expf(m[i]); se += m[i]; }
            float inv = __fdividef(1.f, se);
            #pragma unroll
            for (int i = 0; i < 8; i++) Xg[128 + b * 64 + i * 8 + v] = m[i] * inv;
        }
    }
    __syncwarp();

    // ================= W row v in registers
    float Wr[2][8];
    #pragma unroll
    for (int b = 0; b < 2; b++) {
        const float4* ap = (const float4*)(adj  + (b0 + b) * 64 + v * 8);
        const float4* ep = (const float4*)(edge + (b0 + b) * 64 + v * 8);
        float4 a0 = ap[0], a1 = ap[1], e0 = ep[0], e1 = ep[1];
        float4 S0 = *(const float4*)(Xg + 128 + b * 64 + v * 8);
        float4 S1 = *(const float4*)(Xg + 128 + b * 64 + v * 8 + 4);
        Wr[b][0] = a0.x * (S0.x + e0.x); Wr[b][1] = a0.y * (S0.y + e0.y);
        Wr[b][2] = a0.z * (S0.z + e0.z); Wr[b][3] = a0.w * (S0.w + e0.w);
        Wr[b][4] = a1.x * (S1.x + e1.x); Wr[b][5] = a1.y * (S1.y + e1.y);
        Wr[b][6] = a1.z * (S1.z + e1.z); Wr[b][7] = a1.w * (S1.w + e1.w);
    }

    // ================= h1 row v (j-paired)
    u64 h[2][8];
    #pragma unroll
    for (int i = 0; i < 8; i++) { h[0][i] = 0ull; h[1][i] = 0ull; }
    #pragma unroll
    for (int w = 0; w < 8; w++) {
        u64 w0 = pk1(Wr[0][w]), w1p = pk1(Wr[1][w]);
        const ulonglong2* pr0 = (const ulonglong2*)(Xg + 256 + w * 16);
        const ulonglong2* pr1 = (const ulonglong2*)(Xg + 256 + 128 + w * 16);
        #pragma unroll
        for (int jj = 0; jj < 4; jj++) {
            ulonglong2 r0 = pr0[jj], r1 = pr1[jj];
            h[0][jj * 2]     = fma2_(w0, r0.x, h[0][jj * 2]);
            h[0][jj * 2 + 1] = fma2_(w0, r0.y, h[0][jj * 2 + 1]);
            h[1][jj * 2]     = fma2_(w1p, r1.x, h[1][jj * 2]);
            h[1][jj * 2 + 1] = fma2_(w1p, r1.y, h[1][jj * 2 + 1]);
        }
    }
    float hs[2][16];
    #pragma unroll
    for (int i = 0; i < 8; i++) {
        u64 b1p = ((const u64*)c_w.b1)[i];
        u64 t0 = add2_(h[0][i], b1p), t1 = add2_(h[1][i], b1p);
        up2(t0, hs[0][2 * i], hs[0][2 * i + 1]);
        up2(t1, hs[1][2 * i], hs[1][2 * i + 1]);
    }
    #pragma unroll
    for (int i = 0; i < 16; i++) { hs[0][i] = lrelu(hs[0][i]); hs[1][i] = lrelu(hs[1][i]); }

    // ================= q row v (k-paired)
    u64 qa[2][4];
    #pragma unroll
    for (int i = 0; i < 4; i++) { qa[0][i] = 0ull; qa[1][i] = 0ull; }
    #pragma unroll
    for (int j = 0; j < 16; j++) {
        const ulonglong2* w2r = (const ulonglong2*)c_w.w2[j];
        ulonglong2 wA = w2r[0], wB = w2r[1];
        u64 hj0 = pk1(hs[0][j]), hj1 = pk1(hs[1][j]);
        qa[0][0] = fma2_(hj0, wA.x, qa[0][0]);
        qa[0][1] = fma2_(hj0, wA.y, qa[0][1]);
        qa[0][2] = fma2_(hj0, wB.x, qa[0][2]);
        qa[0][3] = fma2_(hj0, wB.y, qa[0][3]);
        qa[1][0] = fma2_(hj1, wA.x, qa[1][0]);
        qa[1][1] = fma2_(hj1, wA.y, qa[1][1]);
        qa[1][2] = fma2_(hj1, wB.x, qa[1][2]);
        qa[1][3] = fma2_(hj1, wB.y, qa[1][3]);
    }
    __syncwarp();   // S reads done before q overwrites that region
    {
        ulonglong2* d0 = (ulonglong2*)((u64*)(Xg + 128) + v * 4);
        d0[0] = make_ulonglong2(qa[0][0], qa[0][1]);
        d0[1] = make_ulonglong2(qa[0][2], qa[0][3]);
        ulonglong2* d1 = (ulonglong2*)((u64*)(Xg + 128) + 32 + v * 4);
        d1[0] = make_ulonglong2(qa[1][0], qa[1][1]);
        d1[1] = make_ulonglong2(qa[1][2], qa[1][3]);
    }
    __syncwarp();

    // ================= h2 row v (k-paired), write h2 rows
    {
        u64 h2a[2][4];
        #pragma unroll
        for (int i = 0; i < 4; i++) { h2a[0][i] = 0ull; h2a[1][i] = 0ull; }
        #pragma unroll
        for (int w = 0; w < 8; w++) {
            u64 w0 = pk1(Wr[0][w]), w1p = pk1(Wr[1][w]);
            ulonglong2 r0a = *(const ulonglong2*)(Xg + 128 + w * 8);
            ulonglong2 r0b = *(const ulonglong2*)(Xg + 128 + w * 8 + 4);
            ulonglong2 r1a = *(const ulonglong2*)(Xg + 128 + 64 + w * 8);
            ulonglong2 r1b = *(const ulonglong2*)(Xg + 128 + 64 + w * 8 + 4);
            h2a[0][0] = fma2_(w0, r0a.x, h2a[0][0]);
            h2a[0][1] = fma2_(w0, r0a.y, h2a[0][1]);
            h2a[0][2] = fma2_(w0, r0b.x, h2a[0][2]);
            h2a[0][3] = fma2_(w0, r0b.y, h2a[0][3]);
            h2a[1][0] = fma2_(w1p, r1a.x, h2a[1][0]);
            h2a[1][1] = fma2_(w1p, r1a.y, h2a[1][1]);
            h2a[1][2] = fma2_(w1p, r1b.x, h2a[1][2]);
            h2a[1][3] = fma2_(w1p, r1b.y, h2a[1][3]);
        }
        #pragma unroll
        for (int b = 0; b < 2; b++) {
            u64 t0 = add2_(h2a[b][0], ((const u64*)c_w.b2)[0]);
            u64 t1 = add2_(h2a[b][1], ((const u64*)c_w.b2)[1]);
            u64 t2 = add2_(h2a[b][2], ((const u64*)c_w.b2)[2]);
            u64 t3 = add2_(h2a[b][3], ((const u64*)c_w.b2)[3]);
            float e0, e1, e2, e3, e4, e5, e6, e7;
            up2(t0, e0, e1); up2(t1, e2, e3); up2(t2, e4, e5); up2(t3, e6, e7);
            ulonglong2* dst = (ulonglong2*)((u64*)(Xg + 256) + b * 32 + v * 4);
            dst[0] = make_ulonglong2(pk2(lrelu(e0), lrelu(e1)), pk2(lrelu(e2), lrelu(e3)));
            dst[1] = make_ulonglong2(pk2(lrelu(e4), lrelu(e5)), pk2(lrelu(e6), lrelu(e7)));
        }
    }
    __syncwarp();

    // ================= attention pooling: thread v = output channel o
    // Complementary-mask softmax: exp(mask*d+bg) = (mask ? e^{d+bg} : e^{bg});
    // one exp per (b,u) + one hoisted e^{bg}. Shift-free (logits are O(1)).
    float xpv[2];
    {
        const ulonglong2* wgr = (const ulonglong2*)c_w.wg[v];
        ulonglong2 wgA = wgr[0], wgB = wgr[1];
        float d[2][8], ho[2][8], tyu[2][8];
        #pragma unroll
        for (int u = 0; u < 8; u++) {
            const int srcLane = ((g & 3) << 3) | u;
            tyu[0][u] = __shfl_sync(0xffffffffu, tyR[0], srcLane, 32);
            tyu[1][u] = __shfl_sync(0xffffffffu, tyR[1], srcLane, 32);
            #pragma unroll
            for (int b = 0; b < 2; b++) {
                ulonglong2 ra = *(const ulonglong2*)(Xg + 256 + b * 64 + u * 8);
                ulonglong2 rb = *(const ulonglong2*)(Xg + 256 + b * 64 + u * 8 + 4);
                u64 acc = mul2_(wgA.x, ra.x);
                acc = fma2_(wgA.y, ra.y, acc);
                acc = fma2_(wgB.x, rb.x, acc);
                acc = fma2_(wgB.y, rb.y, acc);
                float lo, hi; up2(acc, lo, hi);
                d[b][u] = lo + hi;
                ho[b][u] = Xg[256 + b * 64 + u * 8 + v];
            }
        }
        const float bgv = c_w.bg[v];
        const float ebg = __expf(bgv);
        #pragma unroll
        for (int b = 0; b < 2; b++) {
            float se0 = 0.f, se1 = 0.f, nu0 = 0.f, nu1 = 0.f;
            #pragma unroll
            for (int u = 0; u < 8; u++) {
                float e  = __expf(d[b][u] + bgv);
                float pm = e * ho[b][u];
                bool sel = (tyu[b][u] == 1.0f);
                se1 += sel ? e   : ebg;
                nu1 += sel ? pm  : 0.f;
                se0 += sel ? ebg : e;
                nu0 += sel ? 0.f : pm;
            }
            xpv[b] = 0.5f * __fdividef(nu0 * se1 + nu1 * se0, se0 * se1);
        }
    }

    // ================= final linear via in-group shuffle reduction
    {
        u64 w01 = pk2(c_w.wf[v], c_w.wf[8 + v]);   // lanes = (class0, class1)
        u64 c0 = mul2_(pk1(xpv[0]), w01);
        u64 c1 = mul2_(pk1(xpv[1]), w01);
        #pragma unroll
        for (int m = 1; m < 8; m <<= 1) {
            c0 = add2_(c0, shfl_xor64(c0, m));
            c1 = add2_(c1, shfl_xor64(c1, m));
        }
        if (v == 0) {
            u64 bfp = pk2(c_w.bf[0], c_w.bf[1]);
            c0 = add2_(c0, bfp);
            c1 = add2_(c1, bfp);
            *(ulonglong2*)(out + b0 * 2) = make_ulonglong2(c0, c1);
        }
    }
}

extern "C" void kernel_launch(void* const* d_in, const int* in_sizes, int n_in,
                              void* d_out, int out_size)
{
    const float* x    = (const float*)d_in[0];
    const float* adj  = (const float*)d_in[1];
    const float* edge = (const float*)d_in[2];
    const float* wb = (const float*)d_in[5];
    const float* bb = (const float*)d_in[6];
    const float* w1 = (const float*)d_in[7];
    const float* b1 = (const float*)d_in[8];
    const float* w2 = (const float*)d_in[9];
    const float* b2 = (const float*)d_in[10];
    const float* wg = (const float*)d_in[11];
    const float* bg = (const float*)d_in[12];
    const float* wf = (const float*)d_in[13];
    const float* bf = (const float*)d_in[14];

    void* cwAddr = nullptr;
    cudaGetSymbolAddress(&cwAddr, c_w);
    prep_kernel<<<1, 256>>>((WPack*)cwAddr, wb, bb, w1, b1, w2, b2, wg, bg, wf, bf);

    const int B = in_sizes[0] / 264;
    const int grid = B / (2 * PAIRS_PER_BLOCK);   // 131072 / 32 = 4096, exact
    gcn_kernel<<<grid, NTHREADS>>>(x, adj, edge, (float*)d_out);
}

// round 15
// speedup vs baseline: 1.0252x; 1.0252x over previous
#include <cuda_runtime.h>

#define PAIRS_PER_BLOCK 16
#define NTHREADS (PAIRS_PER_BLOCK * 8)   // 128 threads, 4 warps, no block-wide syncs
#define SLOT 536            // floats per pair slot; 536 % 32 == 24 -> warp group bases {0,24,16,8}
#define BSTRIDE 268         // floats per batch inside slot; 268 % 32 == 12

typedef unsigned long long u64;
typedef unsigned int u32;

struct WPack {
    float w1[32][16];
    float wbT[32][8];
    float w2[16][8];
    float wg[8][8];
    float bb[8];
    float b1[16];
    float b2[8];
    float bg[8];
    float wf[16];
    float bf[2];
};

__constant__ WPack c_w;

// Prep writes packed/transposed weights DIRECTLY into c_w's backing store.
__global__ void prep_kernel(WPack* __restrict__ cw,
                            const float* __restrict__ wb, const float* __restrict__ bb,
                            const float* __restrict__ w1, const float* __restrict__ b1,
                            const float* __restrict__ w2, const float* __restrict__ b2,
                            const float* __restrict__ wg, const float* __restrict__ bg,
                            const float* __restrict__ wf, const float* __restrict__ bf)
{
    int t = threadIdx.x;
    // w1: 512 floats = 128 float4, contiguous copy
    if (t < 128) ((float4*)cw->w1)[t] = ((const float4*)w1)[t];
    for (int i = t; i < 256; i += blockDim.x) {
        int c = i >> 3, o = i & 7;
        cw->wbT[c][o] = wb[o * 32 + c];
    }
    if (t < 32) ((float4*)cw->w2)[t] = ((const float4*)w2)[t];
    if (t >= 32 && t < 48) ((float4*)cw->wg)[t - 32] = ((const float4*)wg)[t - 32];
    if (t < 16) { cw->b1[t] = b1[t]; cw->wf[t] = wf[t]; }
    if (t < 8)  { cw->bb[t] = bb[t]; cw->b2[t] = b2[t]; cw->bg[t] = bg[t]; }
    if (t < 2)  { cw->bf[t] = bf[t]; }
}

__device__ __forceinline__ u64 pk2(float a, float b) {
    u64 r; asm("mov.b64 %0,{%1,%2};" : "=l"(r) : "f"(a), "f"(b)); return r;
}
__device__ __forceinline__ u64 pk1(float a) { return pk2(a, a); }
__device__ __forceinline__ void up2(u64 v, float& a, float& b) {
    asm("mov.b64 {%0,%1},%2;" : "=f"(a), "=f"(b) : "l"(v));
}
__device__ __forceinline__ u64 fma2_(u64 a, u64 b, u64 c) {
    u64 d; asm("fma.rn.f32x2 %0,%1,%2,%3;" : "=l"(d) : "l"(a), "l"(b), "l"(c)); return d;
}
__device__ __forceinline__ u64 add2_(u64 a, u64 b) {
    u64 d; asm("add.rn.f32x2 %0,%1,%2;" : "=l"(d) : "l"(a), "l"(b)); return d;
}
__device__ __forceinline__ u64 mul2_(u64 a, u64 b) {
    u64 d; asm("mul.rn.f32x2 %0,%1,%2;" : "=l"(d) : "l"(a), "l"(b)); return d;
}
__device__ __forceinline__ u64 shfl_xor64(u64 v, int m) {
    return __shfl_xor_sync(0xffffffffu, v, m, 32);
}
__device__ __forceinline__ u32 smem_u32(const void* p) {
    u32 a;
    asm("{ .reg .u64 t; cvta.to.shared.u64 t, %1; cvt.u32.u64 %0, t; }"
        : "=r"(a) : "l"(p));
    return a;
}
__device__ __forceinline__ float lrelu(float x) { return fmaxf(x, 0.01f * x); }

__global__ void __launch_bounds__(NTHREADS, 6)
gcn_kernel(const float* __restrict__ x,   const float* __restrict__ adj,
           const float* __restrict__ edge,
           float* __restrict__ out)
{
    // Per-pair slot (SLOT floats):
    //  Phase A (x stage via cp.async): batch bb at bb*BSTRIDE .. +263
    //  Phase B aliases x region: FkT 0..127, S->q 128..255, p->h2 256..511
    __shared__ __align__(16) float s_u[PAIRS_PER_BLOCK * SLOT];

    const int tid = threadIdx.x;
    const int g = tid >> 3;                      // 0..15
    const int v = tid & 7;
    const size_t pair = (size_t)blockIdx.x * PAIRS_PER_BLOCK + g;
    const size_t b0 = pair * 2;

    {   // warp-local, div-free cp.async staging: lane owns (batch, float4-column)
        // x is independent of c_w -> runs under PDL overlap with prep_kernel.
        const int lane = tid & 31;
        const int wrp  = tid >> 5;               // 0..3
        const int bl   = lane >> 2;              // local batch within warp: 0..7
        const int pr   = wrp * 4 + (bl >> 1);    // pair slot within block: 0..15
        const int bbx  = bl & 1;
        const int jb   = lane & 3;               // float4 column phase
        const float4* src = (const float4*)(x + (size_t)blockIdx.x * (PAIRS_PER_BLOCK * 2 * 264))
                            + (size_t)(wrp * 8 + bl) * 66 + jb;
        u32 dst = smem_u32(s_u) + (u32)(pr * SLOT + bbx * BSTRIDE + jb * 4) * 4u;
        #pragma unroll
        for (int k = 0; k < 16; k++) {
            asm volatile("cp.async.cg.shared.global [%0], [%1], 16;"
                         :: "r"(dst), "l"(src));
            dst += 64; src += 4;
        }
        if (jb < 2) {   // j = jb + 64 in {64,65} < 66
            asm volatile("cp.async.cg.shared.global [%0], [%1], 16;"
                         :: "r"(dst), "l"(src));
        }
        asm volatile("cp.async.commit_group;");
    }

    // PDL: wait for prep_kernel (writer of c_w) to complete before any
    // constant-bank read. Staging LDGs above already in flight.
    cudaGridDependencySynchronize();

    asm volatile("cp.async.wait_group 0;");
    __syncwarp();   // staging is warp-private -> no block barrier needed

    float* Xg = s_u + g * SLOT;

    // node types for THIS thread's node -> registers (pool peers come via shfl)
    float tyR[2];
    tyR[0] = Xg[0 * BSTRIDE + v * 33];
    tyR[1] = Xg[1 * BSTRIDE + v * 33];

    // ================= phase 1: Fk column v (o-paired), p row v (j-paired)
    u64 Fk[2][4], p[2][8];
    #pragma unroll
    for (int i = 0; i < 4; i++) { Fk[0][i] = 0ull; Fk[1][i] = 0ull; }
    #pragma unroll
    for (int i = 0; i < 8; i++) { p[0][i] = 0ull; p[1][i] = 0ull; }

    const float* f0 = Xg + 0 * BSTRIDE + v * 33 + 1;
    const float* f1 = Xg + 1 * BSTRIDE + v * 33 + 1;
    #pragma unroll 8
    for (int c = 0; c < 32; c++) {
        u64 q0 = pk1(f0[c]), q1 = pk1(f1[c]);
        const ulonglong2* w1r = (const ulonglong2*)c_w.w1[c];
        const ulonglong2* wbr = (const ulonglong2*)c_w.wbT[c];
        #pragma unroll
        for (int jj = 0; jj < 4; jj++) {
            ulonglong2 w = w1r[jj];
            p[0][jj * 2]     = fma2_(q0, w.x, p[0][jj * 2]);
            p[0][jj * 2 + 1] = fma2_(q0, w.y, p[0][jj * 2 + 1]);
            p[1][jj * 2]     = fma2_(q1, w.x, p[1][jj * 2]);
            p[1][jj * 2 + 1] = fma2_(q1, w.y, p[1][jj * 2 + 1]);
        }
        #pragma unroll
        for (int oo = 0; oo < 2; oo++) {
            ulonglong2 w = wbr[oo];
            Fk[0][oo * 2]     = fma2_(q0, w.x, Fk[0][oo * 2]);
            Fk[0][oo * 2 + 1] = fma2_(q0, w.y, Fk[0][oo * 2 + 1]);
            Fk[1][oo * 2]     = fma2_(q1, w.x, Fk[1][oo * 2]);
            Fk[1][oo * 2 + 1] = fma2_(q1, w.y, Fk[1][oo * 2 + 1]);
        }
    }
    #pragma unroll
    for (int i = 0; i < 4; i++) {
        u64 bbp = ((const u64*)c_w.bb)[i];
        Fk[0][i] = add2_(Fk[0][i], bbp);
        Fk[1][i] = add2_(Fk[1][i], bbp);
    }

    __syncwarp();   // feat reads done -> alias x region
    {
        ulonglong2* d0 = (ulonglong2*)((u64*)Xg + v * 4);
        d0[0] = make_ulonglong2(Fk[0][0], Fk[0][1]);
        d0[1] = make_ulonglong2(Fk[0][2], Fk[0][3]);
        ulonglong2* d1 = (ulonglong2*)((u64*)Xg + 32 + v * 4);
        d1[0] = make_ulonglong2(Fk[1][0], Fk[1][1]);
        d1[1] = make_ulonglong2(Fk[1][2], Fk[1][3]);
        ulonglong2* p0 = (ulonglong2*)((u64*)(Xg + 256) + v * 8);
        p0[0] = make_ulonglong2(p[0][0], p[0][1]);
        p0[1] = make_ulonglong2(p[0][2], p[0][3]);
        p0[2] = make_ulonglong2(p[0][4], p[0][5]);
        p0[3] = make_ulonglong2(p[0][6], p[0][7]);
        ulonglong2* p1 = (ulonglong2*)((u64*)(Xg + 256) + 64 + v * 8);
        p1[0] = make_ulonglong2(p[1][0], p[1][1]);
        p1[1] = make_ulonglong2(p[1][2], p[1][3]);
        p1[2] = make_ulonglong2(p[1][4], p[1][5]);
        p1[3] = make_ulonglong2(p[1][6], p[1][7]);
    }
    __syncwarp();

    // ================= M column v, softmax over rows (shift-free), write S rows
    {
        float fks[2][8];
        #pragma unroll
        for (int i = 0; i < 4; i++) {
            up2(Fk[0][i], fks[0][2 * i], fks[0][2 * i + 1]);
            up2(Fk[1][i], fks[1][2 * i], fks[1][2 * i + 1]);
        }
        u64 Mv[2][4];
        #pragma unroll
        for (int i = 0; i < 4; i++) { Mv[0][i] = 0ull; Mv[1][i] = 0ull; }
        #pragma unroll
        for (int k = 0; k < 8; k++) {
            ulonglong2 r0a = *(const ulonglong2*)(Xg + k * 8);
            ulonglong2 r0b = *(const ulonglong2*)(Xg + k * 8 + 4);
            ulonglong2 r1a = *(const ulonglong2*)(Xg + 64 + k * 8);
            ulonglong2 r1b = *(const ulonglong2*)(Xg + 64 + k * 8 + 4);
            u64 s0 = pk1(fks[0][k]), s1 = pk1(fks[1][k]);
            Mv[0][0] = fma2_(s0, r0a.x, Mv[0][0]);
            Mv[0][1] = fma2_(s0, r0a.y, Mv[0][1]);
            Mv[0][2] = fma2_(s0, r0b.x, Mv[0][2]);
            Mv[0][3] = fma2_(s0, r0b.y, Mv[0][3]);
            Mv[1][0] = fma2_(s1, r1a.x, Mv[1][0]);
            Mv[1][1] = fma2_(s1, r1a.y, Mv[1][1]);
            Mv[1][2] = fma2_(s1, r1b.x, Mv[1][2]);
            Mv[1][3] = fma2_(s1, r1b.y, Mv[1][3]);
        }
        #pragma unroll
        for (int b = 0; b < 2; b++) {
            float m[8];
            #pragma unroll
            for (int i = 0; i < 4; i++) up2(Mv[b][i], m[2 * i], m[2 * i + 1]);
            float se = 0.f;
            #pragma unroll
            for (int i = 0; i < 8; i++) { m[i] = __expf(m[i]); se += m[i]; }
            float inv = __fdividef(1.f, se);
            #pragma unroll
            for (int i = 0; i < 8; i++) Xg[128 + b * 64 + i * 8 + v] = m[i] * inv;
        }
    }
    __syncwarp();

    // ================= W row v in registers
    float Wr[2][8];
    #pragma unroll
    for (int b = 0; b < 2; b++) {
        const float4* ap = (const float4*)(adj  + (b0 + b) * 64 + v * 8);
        const float4* ep = (const float4*)(edge + (b0 + b) * 64 + v * 8);
        float4 a0 = ap[0], a1 = ap[1], e0 = ep[0], e1 = ep[1];
        float4 S0 = *(const float4*)(Xg + 128 + b * 64 + v * 8);
        float4 S1 = *(const float4*)(Xg + 128 + b * 64 + v * 8 + 4);
        Wr[b][0] = a0.x * (S0.x + e0.x); Wr[b][1] = a0.y * (S0.y + e0.y);
        Wr[b][2] = a0.z * (S0.z + e0.z); Wr[b][3] = a0.w * (S0.w + e0.w);
        Wr[b][4] = a1.x * (S1.x + e1.x); Wr[b][5] = a1.y * (S1.y + e1.y);
        Wr[b][6] = a1.z * (S1.z + e1.z); Wr[b][7] = a1.w * (S1.w + e1.w);
    }

    // ================= h1 row v (j-paired)
    u64 h[2][8];
    #pragma unroll
    for (int i = 0; i < 8; i++) { h[0][i] = 0ull; h[1][i] = 0ull; }
    #pragma unroll
    for (int w = 0; w < 8; w++) {
        u64 w0 = pk1(Wr[0][w]), w1p = pk1(Wr[1][w]);
        const ulonglong2* pr0 = (const ulonglong2*)(Xg + 256 + w * 16);
        const ulonglong2* pr1 = (const ulonglong2*)(Xg + 256 + 128 + w * 16);
        #pragma unroll
        for (int jj = 0; jj < 4; jj++) {
            ulonglong2 r0 = pr0[jj], r1 = pr1[jj];
            h[0][jj * 2]     = fma2_(w0, r0.x, h[0][jj * 2]);
            h[0][jj * 2 + 1] = fma2_(w0, r0.y, h[0][jj * 2 + 1]);
            h[1][jj * 2]     = fma2_(w1p, r1.x, h[1][jj * 2]);
            h[1][jj * 2 + 1] = fma2_(w1p, r1.y, h[1][jj * 2 + 1]);
        }
    }
    float hs[2][16];
    #pragma unroll
    for (int i = 0; i < 8; i++) {
        u64 b1p = ((const u64*)c_w.b1)[i];
        u64 t0 = add2_(h[0][i], b1p), t1 = add2_(h[1][i], b1p);
        up2(t0, hs[0][2 * i], hs[0][2 * i + 1]);
        up2(t1, hs[1][2 * i], hs[1][2 * i + 1]);
    }
    #pragma unroll
    for (int i = 0; i < 16; i++) { hs[0][i] = lrelu(hs[0][i]); hs[1][i] = lrelu(hs[1][i]); }

    // ================= q row v (k-paired)
    u64 qa[2][4];
    #pragma unroll
    for (int i = 0; i < 4; i++) { qa[0][i] = 0ull; qa[1][i] = 0ull; }
    #pragma unroll
    for (int j = 0; j < 16; j++) {
        const ulonglong2* w2r = (const ulonglong2*)c_w.w2[j];
        ulonglong2 wA = w2r[0], wB = w2r[1];
        u64 hj0 = pk1(hs[0][j]), hj1 = pk1(hs[1][j]);
        qa[0][0] = fma2_(hj0, wA.x, qa[0][0]);
        qa[0][1] = fma2_(hj0, wA.y, qa[0][1]);
        qa[0][2] = fma2_(hj0, wB.x, qa[0][2]);
        qa[0][3] = fma2_(hj0, wB.y, qa[0][3]);
        qa[1][0] = fma2_(hj1, wA.x, qa[1][0]);
        qa[1][1] = fma2_(hj1, wA.y, qa[1][1]);
        qa[1][2] = fma2_(hj1, wB.x, qa[1][2]);
        qa[1][3] = fma2_(hj1, wB.y, qa[1][3]);
    }
    __syncwarp();   // S reads done before q overwrites that region
    {
        ulonglong2* d0 = (ulonglong2*)((u64*)(Xg + 128) + v * 4);
        d0[0] = make_ulonglong2(qa[0][0], qa[0][1]);
        d0[1] = make_ulonglong2(qa[0][2], qa[0][3]);
        ulonglong2* d1 = (ulonglong2*)((u64*)(Xg + 128) + 32 + v * 4);
        d1[0] = make_ulonglong2(qa[1][0], qa[1][1]);
        d1[1] = make_ulonglong2(qa[1][2], qa[1][3]);
    }
    __syncwarp();

    // ================= h2 row v (k-paired), write h2 rows
    {
        u64 h2a[2][4];
        #pragma unroll
        for (int i = 0; i < 4; i++) { h2a[0][i] = 0ull; h2a[1][i] = 0ull; }
        #pragma unroll
        for (int w = 0; w < 8; w++) {
            u64 w0 = pk1(Wr[0][w]), w1p = pk1(Wr[1][w]);
            ulonglong2 r0a = *(const ulonglong2*)(Xg + 128 + w * 8);
            ulonglong2 r0b = *(const ulonglong2*)(Xg + 128 + w * 8 + 4);
            ulonglong2 r1a = *(const ulonglong2*)(Xg + 128 + 64 + w * 8);
            ulonglong2 r1b = *(const ulonglong2*)(Xg + 128 + 64 + w * 8 + 4);
            h2a[0][0] = fma2_(w0, r0a.x, h2a[0][0]);
            h2a[0][1] = fma2_(w0, r0a.y, h2a[0][1]);
            h2a[0][2] = fma2_(w0, r0b.x, h2a[0][2]);
            h2a[0][3] = fma2_(w0, r0b.y, h2a[0][3]);
            h2a[1][0] = fma2_(w1p, r1a.x, h2a[1][0]);
            h2a[1][1] = fma2_(w1p, r1a.y, h2a[1][1]);
            h2a[1][2] = fma2_(w1p, r1b.x, h2a[1][2]);
            h2a[1][3] = fma2_(w1p, r1b.y, h2a[1][3]);
        }
        #pragma unroll
        for (int b = 0; b < 2; b++) {
            u64 t0 = add2_(h2a[b][0], ((const u64*)c_w.b2)[0]);
            u64 t1 = add2_(h2a[b][1], ((const u64*)c_w.b2)[1]);
            u64 t2 = add2_(h2a[b][2], ((const u64*)c_w.b2)[2]);
            u64 t3 = add2_(h2a[b][3], ((const u64*)c_w.b2)[3]);
            float e0, e1, e2, e3, e4, e5, e6, e7;
            up2(t0, e0, e1); up2(t1, e2, e3); up2(t2, e4, e5); up2(t3, e6, e7);
            ulonglong2* dst = (ulonglong2*)((u64*)(Xg + 256) + b * 32 + v * 4);
            dst[0] = make_ulonglong2(pk2(lrelu(e0), lrelu(e1)), pk2(lrelu(e2), lrelu(e3)));
            dst[1] = make_ulonglong2(pk2(lrelu(e4), lrelu(e5)), pk2(lrelu(e6), lrelu(e7)));
        }
    }
    __syncwarp();

    // ================= attention pooling: thread v = output channel o
    // Complementary-mask softmax: exp(mask*d+bg) = (mask ? e^{d+bg} : e^{bg});
    // one exp per (b,u) + one hoisted e^{bg}. Shift-free (logits are O(1)).
    float xpv[2];
    {
        const ulonglong2* wgr = (const ulonglong2*)c_w.wg[v];
        ulonglong2 wgA = wgr[0], wgB = wgr[1];
        float d[2][8], ho[2][8], tyu[2][8];
        #pragma unroll
        for (int u = 0; u < 8; u++) {
            const int srcLane = ((g & 3) << 3) | u;
            tyu[0][u] = __shfl_sync(0xffffffffu, tyR[0], srcLane, 32);
            tyu[1][u] = __shfl_sync(0xffffffffu, tyR[1], srcLane, 32);
            #pragma unroll
            for (int b = 0; b < 2; b++) {
                ulonglong2 ra = *(const ulonglong2*)(Xg + 256 + b * 64 + u * 8);
                ulonglong2 rb = *(const ulonglong2*)(Xg + 256 + b * 64 + u * 8 + 4);
                u64 acc = mul2_(wgA.x, ra.x);
                acc = fma2_(wgA.y, ra.y, acc);
                acc = fma2_(wgB.x, rb.x, acc);
                acc = fma2_(wgB.y, rb.y, acc);
                float lo, hi; up2(acc, lo, hi);
                d[b][u] = lo + hi;
                ho[b][u] = Xg[256 + b * 64 + u * 8 + v];
            }
        }
        const float bgv = c_w.bg[v];
        const float ebg = __expf(bgv);
        #pragma unroll
        for (int b = 0; b < 2; b++) {
            float se0 = 0.f, se1 = 0.f, nu0 = 0.f, nu1 = 0.f;
            #pragma unroll
            for (int u = 0; u < 8; u++) {
                float e  = __expf(d[b][u] + bgv);
                float pm = e * ho[b][u];
                bool sel = (tyu[b][u] == 1.0f);
                se1 += sel ? e   : ebg;
                nu1 += sel ? pm  : 0.f;
                se0 += sel ? ebg : e;
                nu0 += sel ? 0.f : pm;
            }
            xpv[b] = 0.5f * __fdividef(nu0 * se1 + nu1 * se0, se0 * se1);
        }
    }

    // ================= final linear via in-group shuffle reduction
    {
        u64 w01 = pk2(c_w.wf[v], c_w.wf[8 + v]);   // lanes = (class0, class1)
        u64 c0 = mul2_(pk1(xpv[0]), w01);
        u64 c1 = mul2_(pk1(xpv[1]), w01);
        #pragma unroll
        for (int m = 1; m < 8; m <<= 1) {
            c0 = add2_(c0, shfl_xor64(c0, m));
            c1 = add2_(c1, shfl_xor64(c1, m));
        }
        if (v == 0) {
            u64 bfp = pk2(c_w.bf[0], c_w.bf[1]);
            c0 = add2_(c0, bfp);
            c1 = add2_(c1, bfp);
            *(ulonglong2*)(out + b0 * 2) = make_ulonglong2(c0, c1);
        }
    }
}

extern "C" void kernel_launch(void* const* d_in, const int* in_sizes, int n_in,
                              void* d_out, int out_size)
{
    const float* x    = (const float*)d_in[0];
    const float* adj  = (const float*)d_in[1];
    const float* edge = (const float*)d_in[2];
    const float* wb = (const float*)d_in[5];
    const float* bb = (const float*)d_in[6];
    const float* w1 = (const float*)d_in[7];
    const float* b1 = (const float*)d_in[8];
    const float* w2 = (const float*)d_in[9];
    const float* b2 = (const float*)d_in[10];
    const float* wg = (const float*)d_in[11];
    const float* bg = (const float*)d_in[12];
    const float* wf = (const float*)d_in[13];
    const float* bf = (const float*)d_in[14];

    void* cwAddr = nullptr;
    cudaGetSymbolAddress(&cwAddr, c_w);
    prep_kernel<<<1, 256>>>((WPack*)cwAddr, wb, bb, w1, b1, w2, b2, wg, bg, wf, bf);

    const int B = in_sizes[0] / 264;
    const int grid = B / (2 * PAIRS_PER_BLOCK);   // 131072 / 32 = 4096, exact

    // PDL launch: gcn_kernel may begin (staging x) while prep_kernel is still
    // running; cudaGridDependencySynchronize() in-kernel gates the c_w reads.
    cudaLaunchConfig_t cfg = {};
    cfg.gridDim  = dim3(grid, 1, 1);
    cfg.blockDim = dim3(NTHREADS, 1, 1);
    cudaLaunchAttribute attrs[1];
    attrs[0].id = cudaLaunchAttributeProgrammaticStreamSerialization;
    attrs[0].val.programmaticStreamSerializationAllowed = 1;
    cfg.attrs = attrs;
    cfg.numAttrs = 1;
    cudaLaunchKernelEx(&cfg, gcn_kernel, x, adj, edge, (float*)d_out);
}